// round 6
// baseline (speedup 1.0000x reference)
#include <cuda_runtime.h>
#include <cuda_bf16.h>
#include <cuda_fp16.h>
#include <math.h>
#include <stdint.h>

// ---------------------------------------------------------------------------
// GatedBlock via mma.sync implicit GEMM.
//   main term : fp16 hi GEMM (m16n8k16.f16, fp32 accum)
//   correction: one e4m3 fp8 GEMM (m16n8k32) computing xl*wh + xh*wl,
//               K-concatenated, combined scale 2^16.
//   conv3d(72->176, k5, pad2)  ==>  D[M=128 spatial, N=176 co], K = 72*128
//   gate fused into the GEMM epilogue, then depthwise gaussian stride-2.
// ---------------------------------------------------------------------------

#define B_      4
#define CI_     72
#define CO_     176
#define NSP_    (32*32*32)
#define NCH_    144

#define KC_     64            // K per chunk (fp16); fp8 K = 128
#define NCHUNK_ 144           // 72*128 / 64
#define AH_TILE 16384         // 128 rows x 64 fp16
#define A8_TILE 16384         // 128 rows x 128 fp8
#define BH_TILE 22528         // 176 rows x 64 fp16
#define B8_TILE 22528         // 176 rows x 128 fp8
#define NT_     512

__device__ float g_z[(size_t)B_ * NCH_ * NSP_];
__device__ __half  g_wbh[(size_t)NCHUNK_ * CO_ * KC_];   // fp16 hi, pre-swizzled
__device__ uint8_t g_w8[(size_t)NCHUNK_ * B8_TILE];      // [wh*2^6 | wl*2^16] e4m3

// ---- smem byte offsets (dynamic smem) ----
#define SA_OFF    0                        // Ah: 2 x 16384 = 32768
#define SA8_OFF   32768                    // A8: 2 x 16384 -> 65536
#define SB_OFF    65536                    // Bh: 2 x 22528 -> 110592
#define SB8_OFF   110592                   // B8: 2 x 22528 -> 155648
#define SX_OFF    155648                   // xs: 1584 floats
#define XS_FLOATS 1584
#define ST_OFF    161984                   // tapoff: 128 ints
#define SSB_OFF   162496
#define SGB_OFF   162560
#define SMEM_TOTAL 162816

// ---------------- helpers ----------------
__device__ __forceinline__ uint32_t smem_u32(const void* p){
    uint32_t a;
    asm("{ .reg .u64 t; cvta.to.shared.u64 t, %1; cvt.u32.u64 %0, t; }"
        : "=r"(a) : "l"(p));
    return a;
}
__device__ __forceinline__ uint32_t swz(uint32_t o){
    return o ^ (((o >> 7) & 7u) << 4);
}

#define CPA16(d,s) asm volatile("cp.async.cg.shared.global [%0], [%1], 16;" :: "r"(d), "l"(s))
#define CPA8(d,s)  asm volatile("cp.async.ca.shared.global [%0], [%1], 8;"  :: "r"(d), "l"(s))
#define CPC()      asm volatile("cp.async.commit_group;")
#define CPW0()     asm volatile("cp.async.wait_group 0;")

#define LDM4(r, a) \
    asm volatile("ldmatrix.sync.aligned.m8n8.x4.shared.b16 {%0,%1,%2,%3}, [%4];" \
        : "=r"((r)[0]),"=r"((r)[1]),"=r"((r)[2]),"=r"((r)[3]) : "r"(a))
#define LDM2(r, a) \
    asm volatile("ldmatrix.sync.aligned.m8n8.x2.shared.b16 {%0,%1}, [%2];" \
        : "=r"((r)[0]),"=r"((r)[1]) : "r"(a))

#define MMAF16(d, a, b0v, b1v) \
    asm volatile("mma.sync.aligned.m16n8k16.row.col.f32.f16.f16.f32 " \
        "{%0,%1,%2,%3}, {%4,%5,%6,%7}, {%8,%9}, {%0,%1,%2,%3};" \
        : "+f"((d)[0]),"+f"((d)[1]),"+f"((d)[2]),"+f"((d)[3]) \
        : "r"((a)[0]),"r"((a)[1]),"r"((a)[2]),"r"((a)[3]), "r"(b0v), "r"(b1v))

#define MMAFP8(d, a, b0v, b1v) \
    asm volatile("mma.sync.aligned.m16n8k32.row.col.f32.e4m3.e4m3.f32 " \
        "{%0,%1,%2,%3}, {%4,%5,%6,%7}, {%8,%9}, {%0,%1,%2,%3};" \
        : "+f"((d)[0]),"+f"((d)[1]),"+f"((d)[2]),"+f"((d)[3]) \
        : "r"((a)[0]),"r"((a)[1]),"r"((a)[2]),"r"((a)[3]), "r"(b0v), "r"(b1v))

// d.hi = src1, d.lo = src2
#define CVT_E4M3X2(d, hi, lo) \
    asm("cvt.rn.satfinite.e4m3x2.f32 %0, %1, %2;" : "=h"(d) : "f"(hi), "f"(lo))

// ---------------------------------------------------------------------------
// Weight prep: reorder to K=(ci*128+tap); fp16 hi pre-swizzled; fp8 image
// [wh*2^6 | wl*2^16] e4m3, pre-swizzled 128B rows.
// ---------------------------------------------------------------------------
__global__ void prep_kernel(const float* __restrict__ W)
{
    int e = blockIdx.x * 256 + threadIdx.x;   // 144*176*64 = 1,622,016 exact
    int col   = e & 63;
    int row   = (e >> 6) % CO_;
    int chunk = e / (CO_ * KC_);
    int k  = chunk * KC_ + col;
    int ci = k >> 7;
    int tap = k & 127;
    float v = (tap < 125) ? W[((size_t)row * CI_ + ci) * 125 + tap] : 0.f;
    __half hh = __float2half_rn(v);
    float hf = __half2float(hh);
    const uint32_t rx = (uint32_t)(row & 7) << 4;

    uint32_t sw16 = ((uint32_t)(row * 128 + col * 2)) ^ rx;
    g_wbh[(size_t)chunk * (CO_ * KC_) + (sw16 >> 1)] = hh;

    unsigned short t;
    CVT_E4M3X2(t, 0.f, hf * 64.f);
    g_w8[(size_t)chunk * B8_TILE + (((uint32_t)(row * 128 + col)) ^ rx)] =
        (uint8_t)(t & 0xFF);
    CVT_E4M3X2(t, 0.f, (v - hf) * 65536.f);
    g_w8[(size_t)chunk * B8_TILE + (((uint32_t)(row * 128 + 64 + col)) ^ rx)] =
        (uint8_t)(t & 0xFF);
}

// ---------------------------------------------------------------------------
// Main kernel: implicit GEMM + fused gate epilogue.
// grid (8 y-tiles, 32 z, 4 b), 512 threads. warps: 8M x 2N, warp tile 16x88.
// ---------------------------------------------------------------------------
__global__ __launch_bounds__(NT_, 1)
void conv_mma_kernel(const float* __restrict__ x,
                     const float* __restrict__ sbg, const float* __restrict__ gbg)
{
    extern __shared__ unsigned char smem[];
    const uint32_t smb = smem_u32(smem);

    const int tid = threadIdx.x;
    const int wid = tid >> 5;
    const int lid = tid & 31;
    const int b  = blockIdx.z;
    const int z0 = blockIdx.y;
    const int y0 = blockIdx.x * 4;

    // builder role: 16 warps = 4 y-groups x 4 k-quarters
    const int byy = wid & 3, bkq = wid >> 2;
    // mma role: 8 M-groups x 2 N-halves
    const int m0 = (wid >> 1) * 16;
    const int n0 = (wid & 1) * 88;

    float* xs     = (float*)(smem + SX_OFF);
    int*   tapoff = (int*)(smem + ST_OFF);
    float* sS     = (float*)(smem + SSB_OFF);
    float* sG     = (float*)(smem + SGB_OFF);

    for (int i = tid; i < XS_FLOATS; i += NT_) xs[i] = 0.f;
    if (tid < 128) {
        int tap = tid;
        int kd = tap / 25, r = tap % 25;
        int kh = r / 5, kw = r % 5;
        tapoff[tid] = (tap < 125) ? (kd * 8 + kh) * 36 + kw : 1440;
    }
    if (tid < 16) sS[tid] = sbg[tid];
    if (tid < 32) sG[tid] = gbg[tid];
    __syncthreads();

    const float* xb = x + (size_t)b * CI_ * NSP_;

    auto stage_x = [&](int ci) {
        const float* xc = xb + (size_t)ci * NSP_;
        for (int it = tid; it < 640; it += NT_) {
            int ck = it & 15;
            int row = it >> 4;           // zi*8 + yi
            int yi = row & 7, zi = row >> 3;
            int gy = y0 + yi - 2, gz = z0 + zi - 2;
            if ((unsigned)gy < 32u && (unsigned)gz < 32u)
                CPA8(smb + SX_OFF + (uint32_t)(row * 36 + 2 + ck * 2) * 4,
                     xc + ((gz * 32 + gy) * 32 + ck * 2));
        }
    };
    auto stage_B = [&](int n, int nb) {
        const char* srcH = (const char*)g_wbh + (size_t)n * BH_TILE;
        const char* src8 = (const char*)g_w8  + (size_t)n * B8_TILE;
        uint32_t dstH = smb + SB_OFF  + nb * BH_TILE;
        uint32_t dst8 = smb + SB8_OFF + nb * B8_TILE;
        for (int i = tid; i < BH_TILE / 16; i += NT_) {
            CPA16(dstH + i * 16, srcH + i * 16);
            CPA16(dst8 + i * 16, src8 + i * 16);
        }
    };
    auto build_A = [&](int n, int nb) {
        char* Ah = (char*)smem + SA_OFF  + nb * AH_TILE;
        char* A8 = (char*)smem + SA8_OFF + nb * A8_TILE;
        const int tb  = (n & 1) * 64;
        const int lin = byy * 36 + lid;
        const int m   = byy * 32 + lid;
        const uint32_t mx = (uint32_t)(m & 7) << 4;
#pragma unroll
        for (int j = 0; j < 8; ++j) {
            int k0 = bkq * 16 + 2 * j;
            float v0 = xs[tapoff[tb + k0]     + lin];
            float v1 = xs[tapoff[tb + k0 + 1] + lin];
            __half h0 = __float2half_rn(v0);
            __half h1 = __float2half_rn(v1);
            float h0f = __half2float(h0), h1f = __half2float(h1);
            uint32_t hp = (uint32_t)__half_as_ushort(h0) |
                          ((uint32_t)__half_as_ushort(h1) << 16);
            *(uint32_t*)(Ah + (((uint32_t)(m * 128 + k0 * 2)) ^ mx)) = hp;
            unsigned short lp8, hp8;
            CVT_E4M3X2(lp8, (v1 - h1f) * 1024.f, (v0 - h0f) * 1024.f);
            CVT_E4M3X2(hp8, h1f, h0f);
            *(unsigned short*)(A8 + (((uint32_t)(m * 128 + k0)) ^ mx)) = lp8;
            *(unsigned short*)(A8 + (((uint32_t)(m * 128 + 64 + k0)) ^ mx)) = hp8;
        }
    };

    // lane-invariant ldmatrix offsets (same pattern works for b16 k16 and fp8 k32)
    const uint32_t aLane  = (uint32_t)((lid & 15) * 128 + ((lid & 16) ? 16 : 0));
    const uint32_t bLane4 = (uint32_t)((((lid & 7) + ((lid & 16) ? 8 : 0)) * 128) +
                                       ((lid & 8) ? 16 : 0));
    const uint32_t bLane2 = (uint32_t)((lid & 7) * 128 + ((lid & 8) ? 16 : 0));

    float acc[11][4], acc2[11][4];
#pragma unroll
    for (int ni = 0; ni < 11; ++ni)
#pragma unroll
        for (int r = 0; r < 4; ++r) { acc[ni][r] = 0.f; acc2[ni][r] = 0.f; }

    // ---- prologue ----
    stage_B(0, 0);
    stage_x(0);
    CPC(); CPW0();
    __syncthreads();
    build_A(0, 0);
    __syncthreads();

    for (int c = 0; c < NCHUNK_; ++c) {
        const int bsel = c & 1;
        if (c + 1 < NCHUNK_) {
            stage_B(c + 1, bsel ^ 1);
            if (((c + 1) & 1) == 0) stage_x((c + 1) >> 1);
            CPC();
        }

        const uint32_t AhB = smb + SA_OFF  + bsel * AH_TILE;
        const uint32_t A8B = smb + SA8_OFF + bsel * A8_TILE;
        const uint32_t BhB = smb + SB_OFF  + bsel * BH_TILE;
        const uint32_t B8B = smb + SB8_OFF + bsel * B8_TILE;

        // fp16 main term: 4 k16-steps
#pragma unroll
        for (int ks = 0; ks < 4; ++ks) {
            const uint32_t kso = (uint32_t)ks * 32;
            uint32_t ah[4];
            LDM4(ah, AhB + swz((uint32_t)(m0 * 128) + kso + aLane));
#pragma unroll
            for (int nip = 0; nip < 5; ++nip) {
                uint32_t bh[4];
                LDM4(bh, BhB + swz((uint32_t)((n0 + nip * 16) * 128) + kso + bLane4));
                MMAF16(acc[nip * 2],     ah, bh[0], bh[1]);
                MMAF16(acc[nip * 2 + 1], ah, bh[2], bh[3]);
            }
            uint32_t b2[2];
            LDM2(b2, BhB + swz((uint32_t)((n0 + 80) * 128) + kso + bLane2));
            MMAF16(acc[10], ah, b2[0], b2[1]);
        }

        // fp8 correction: 4 k32-steps over [xl | xh] x [wh | wl]
#pragma unroll
        for (int s = 0; s < 4; ++s) {
            const uint32_t so = (uint32_t)s * 32;
            uint32_t a8[4];
            LDM4(a8, A8B + swz((uint32_t)(m0 * 128) + so + aLane));
#pragma unroll
            for (int nip = 0; nip < 5; ++nip) {
                uint32_t b8[4];
                LDM4(b8, B8B + swz((uint32_t)((n0 + nip * 16) * 128) + so + bLane4));
                MMAFP8(acc2[nip * 2],     a8, b8[0], b8[1]);
                MMAFP8(acc2[nip * 2 + 1], a8, b8[2], b8[3]);
            }
            uint32_t b2[2];
            LDM2(b2, B8B + swz((uint32_t)((n0 + 80) * 128) + so + bLane2));
            MMAFP8(acc2[10], a8, b2[0], b2[1]);
        }

        if (c + 1 < NCHUNK_) {
            CPW0();
            __syncthreads();
            build_A(c + 1, bsel ^ 1);
        }
        __syncthreads();
    }

    // ---- epilogue: combine scales, -> smem, sigmoid gates, write g_z ----
    const float corr = 1.f / 65536.f;
    float* sD = (float*)smem;   // [176][132] floats, reuses tile smem
#pragma unroll
    for (int ni = 0; ni < 11; ++ni)
#pragma unroll
        for (int r = 0; r < 4; ++r) {
            int m  = m0 + (lid >> 2) + ((r & 2) ? 8 : 0);
            int cc = n0 + ni * 8 + (lid & 3) * 2 + (r & 1);
            sD[cc * 132 + m] = acc[ni][r] + acc2[ni][r] * corr;
        }
    __syncthreads();

    for (int i = tid; i < 32 * 128; i += NT_) {
        int gi = i >> 7, mm = i & 127;
        int ad = (144 + gi) * 132 + mm;
        sD[ad] = 1.f / (1.f + expf(-(sD[ad] + sG[gi])));
    }
    __syncthreads();

    float* zb = g_z + (size_t)b * NCH_ * NSP_ + (size_t)z0 * 1024 + y0 * 32;
    for (int i = tid; i < 144 * 128; i += NT_) {
        int cc = i >> 7, mm = i & 127;
        float v = sD[cc * 132 + mm];
        float o;
        if (cc < 16) o = fmaxf(v + sS[cc], 0.f);
        else {
            int gi = (cc < 64) ? (cc - 16) / 3 : 16 + (cc - 64) / 5;
            o = v * sD[(144 + gi) * 132 + mm];
        }
        zb[(size_t)cc * NSP_ + mm] = o;
    }
}

// ---------------------------------------------------------------------------
// Depthwise 5^3 gaussian, stride2, pad2 -> (16,16,16). grid (8, 144, 4).
// ---------------------------------------------------------------------------
__global__ __launch_bounds__(256)
void lowpass_kernel(float* __restrict__ out)
{
    const int zt = blockIdx.x;
    const int c  = blockIdx.y;
    const int b  = blockIdx.z;
    const int tid = threadIdx.x;

    __shared__ float sZ[7 * 35 * 35];
    __shared__ float sWg[125];

    if (tid < 125) {
        int kw = tid % 5, t = tid / 5;
        int kh = t % 5,  kd = t / 5;
        double g[5], s = 0.0;
#pragma unroll
        for (int r = 0; r < 5; ++r) {
            double d = (double)(r - 2);
            g[r] = exp(-d * d / 1.5);
            s += g[r];
        }
        sWg[tid] = (float)(g[kd] * g[kh] * g[kw] / (s * s * s));
    }

    const int zo0 = 2 * zt;
    const int zi0 = 2 * zo0 - 2;
    const float* zc = g_z + (size_t)(b * NCH_ + c) * NSP_;

    for (int i = tid; i < 7 * 35 * 35; i += 256) {
        int xi = i % 35;
        int t  = i / 35;
        int yi = t % 35;
        int zi = t / 35;
        int gx = xi - 2, gy = yi - 2, gz = zi0 + zi;
        float v = 0.f;
        if ((unsigned)gx < 32u && (unsigned)gy < 32u && (unsigned)gz < 32u)
            v = zc[(gz * 32 + gy) * 32 + gx];
        sZ[i] = v;
    }
    __syncthreads();

    const int xo = tid & 15;
    const int yo = tid >> 4;
#pragma unroll
    for (int dz = 0; dz < 2; ++dz) {
        float sum = 0.f;
#pragma unroll
        for (int kd = 0; kd < 5; ++kd)
#pragma unroll
            for (int kh = 0; kh < 5; ++kh)
#pragma unroll
                for (int kw = 0; kw < 5; ++kw)
                    sum += sWg[(kd * 5 + kh) * 5 + kw] *
                           sZ[((2 * dz + kd) * 35 + (2 * yo + kh)) * 35 +
                              2 * xo + kw];
        out[((size_t)(b * NCH_ + c) * 16 + (zo0 + dz)) * 256 + yo * 16 + xo] = sum;
    }
}

// ---------------------------------------------------------------------------
extern "C" void kernel_launch(void* const* d_in, const int* in_sizes, int n_in,
                              void* d_out, int out_size)
{
    const float* x  = (const float*)d_in[0];   // (4,72,32,32,32)
    const float* W  = (const float*)d_in[1];   // (176,72,5,5,5)
    const float* sb = (const float*)d_in[2];   // (16,)
    const float* gb = (const float*)d_in[3];   // (32,)
    float* out = (float*)d_out;                // (4,144,16,16,16)

    cudaFuncSetAttribute(conv_mma_kernel,
                         cudaFuncAttributeMaxDynamicSharedMemorySize, SMEM_TOTAL);

    prep_kernel<<<6336, 256>>>(W);
    conv_mma_kernel<<<dim3(8, 32, B_), NT_, SMEM_TOTAL>>>(x, sb, gb);
    lowpass_kernel<<<dim3(8, NCH_, B_), 256>>>(out);
}

// round 7
// speedup vs baseline: 2.0305x; 2.0305x over previous
#include <cuda_runtime.h>
#include <cuda_fp16.h>
#include <math.h>
#include <stdint.h>

// ---------------------------------------------------------------------------
// GatedBlock via mma.sync fp16 implicit GEMM, 2-term weight-split:
//   D = x_f16 * wh + x_f16 * wl   (wh=fp16(w), wl=fp16(w-wh); w exact to 2^-22,
//   only x carries fp16 rounding -> rel_err ~1.5e-4)
//   conv3d(72->176, k5, pad2)  ==>  D[M=128 spatial, N=176 co], K = 72*128
//   gate fused into the GEMM epilogue, then depthwise gaussian stride-2.
// ---------------------------------------------------------------------------

#define B_      4
#define CI_     72
#define CO_     176
#define NSP_    (32*32*32)
#define NCH_    144

#define KC_     64            // K per chunk
#define NCHUNK_ 144           // 72*128 / 64
#define A_TILE  16384         // 128 rows x 64 fp16
#define B_TILE  22528         // 176 rows x 64 fp16 (per hi/lo image)
#define NT_     512

__device__ float g_z[(size_t)B_ * NCH_ * NSP_];
__device__ __half g_wprep[(size_t)NCHUNK_ * 2 * CO_ * KC_];  // [hi|lo] pre-swizzled

// ---- smem byte offsets (dynamic smem) ----
#define SA_OFF    0                        // A: 2 x 16384 = 32768
#define SB_OFF    32768                    // B: 2 x (2 x 22528) -> 122880
#define SX_OFF    122880                   // xs: 1584 floats -> 129216
#define XS_FLOATS 1584
#define ST_OFF    129216                   // tapoff: 128 ints -> 129728
#define SSB_OFF   129728
#define SGB_OFF   129792
#define SMEM_TOTAL 129920

// ---------------- helpers ----------------
__device__ __forceinline__ uint32_t smem_u32(const void* p){
    uint32_t a;
    asm("{ .reg .u64 t; cvta.to.shared.u64 t, %1; cvt.u32.u64 %0, t; }"
        : "=r"(a) : "l"(p));
    return a;
}
__device__ __forceinline__ uint32_t swz(uint32_t o){
    return o ^ (((o >> 7) & 7u) << 4);
}

#define CPA16(d,s) asm volatile("cp.async.cg.shared.global [%0], [%1], 16;" :: "r"(d), "l"(s))
#define CPA8(d,s)  asm volatile("cp.async.ca.shared.global [%0], [%1], 8;"  :: "r"(d), "l"(s))
#define CPC()      asm volatile("cp.async.commit_group;")
#define CPW0()     asm volatile("cp.async.wait_group 0;")

#define LDM4(r, a) \
    asm volatile("ldmatrix.sync.aligned.m8n8.x4.shared.b16 {%0,%1,%2,%3}, [%4];" \
        : "=r"((r)[0]),"=r"((r)[1]),"=r"((r)[2]),"=r"((r)[3]) : "r"(a))
#define LDM2(r, a) \
    asm volatile("ldmatrix.sync.aligned.m8n8.x2.shared.b16 {%0,%1}, [%2];" \
        : "=r"((r)[0]),"=r"((r)[1]) : "r"(a))

#define MMAF16(d, a, b0v, b1v) \
    asm volatile("mma.sync.aligned.m16n8k16.row.col.f32.f16.f16.f32 " \
        "{%0,%1,%2,%3}, {%4,%5,%6,%7}, {%8,%9}, {%0,%1,%2,%3};" \
        : "+f"((d)[0]),"+f"((d)[1]),"+f"((d)[2]),"+f"((d)[3]) \
        : "r"((a)[0]),"r"((a)[1]),"r"((a)[2]),"r"((a)[3]), "r"(b0v), "r"(b1v))

// ---------------------------------------------------------------------------
// Weight prep: reorder to K=(ci*128+tap), split fp16 hi/lo, pre-apply the
// XOR swizzle so the main kernel can cp.async the tiles linearly.
// ---------------------------------------------------------------------------
__global__ void prep_kernel(const float* __restrict__ W)
{
    int e = blockIdx.x * 256 + threadIdx.x;   // 144*176*64 = 1,622,016 exact
    int col   = e & 63;
    int row   = (e >> 6) % CO_;
    int chunk = e / (CO_ * KC_);
    int k  = chunk * KC_ + col;
    int ci = k >> 7;
    int tap = k & 127;
    float v = (tap < 125) ? W[((size_t)row * CI_ + ci) * 125 + tap] : 0.f;
    __half hi = __float2half_rn(v);
    __half lo = __float2half_rn(v - __half2float(hi));
    uint32_t off = (uint32_t)(row * 128 + col * 2);
    uint32_t sw  = off ^ ((uint32_t)(row & 7) << 4);
    size_t base = (size_t)chunk * 2 * (CO_ * KC_);
    g_wprep[base + (sw >> 1)]             = hi;
    g_wprep[base + CO_ * KC_ + (sw >> 1)] = lo;
}

// ---------------------------------------------------------------------------
// Main kernel: implicit GEMM + fused gate epilogue.
// grid (8 y-tiles, 32 z, 4 b), 512 threads. warps: 8M x 2N, warp tile 16x88.
// ---------------------------------------------------------------------------
__global__ __launch_bounds__(NT_, 1)
void conv_mma_kernel(const float* __restrict__ x,
                     const float* __restrict__ sbg, const float* __restrict__ gbg)
{
    extern __shared__ unsigned char smem[];
    const uint32_t smb = smem_u32(smem);

    const int tid = threadIdx.x;
    const int wid = tid >> 5;
    const int lid = tid & 31;
    const int b  = blockIdx.z;
    const int z0 = blockIdx.y;
    const int y0 = blockIdx.x * 4;

    // builder role: 16 warps = 4 y-groups x 4 k-quarters
    const int byy = wid & 3, bkq = wid >> 2;
    // mma role: 8 M-groups x 2 N-halves
    const int m0 = (wid >> 1) * 16;
    const int n0 = (wid & 1) * 88;

    float* xs     = (float*)(smem + SX_OFF);
    int*   tapoff = (int*)(smem + ST_OFF);
    float* sS     = (float*)(smem + SSB_OFF);
    float* sG     = (float*)(smem + SGB_OFF);

    for (int i = tid; i < XS_FLOATS; i += NT_) xs[i] = 0.f;
    if (tid < 128) {
        int tap = tid;
        int kd = tap / 25, r = tap % 25;
        int kh = r / 5, kw = r % 5;
        tapoff[tid] = (tap < 125) ? (kd * 8 + kh) * 36 + kw : 1440;
    }
    if (tid < 16) sS[tid] = sbg[tid];
    if (tid < 32) sG[tid] = gbg[tid];
    __syncthreads();

    const float* xb = x + (size_t)b * CI_ * NSP_;

    auto stage_x = [&](int ci) {
        const float* xc = xb + (size_t)ci * NSP_;
        for (int it = tid; it < 640; it += NT_) {
            int ck = it & 15;
            int row = it >> 4;           // zi*8 + yi
            int yi = row & 7, zi = row >> 3;
            int gy = y0 + yi - 2, gz = z0 + zi - 2;
            if ((unsigned)gy < 32u && (unsigned)gz < 32u)
                CPA8(smb + SX_OFF + (uint32_t)(row * 36 + 2 + ck * 2) * 4,
                     xc + ((gz * 32 + gy) * 32 + ck * 2));
        }
    };
    auto stage_B = [&](int n, int nb) {
        const char* src = (const char*)g_wprep + (size_t)n * (2 * B_TILE);
        uint32_t dst = smb + SB_OFF + nb * (2 * B_TILE);
        for (int i = tid; i < (2 * B_TILE) / 16; i += NT_)
            CPA16(dst + i * 16, src + i * 16);
    };
    auto build_A = [&](int n, int nb) {
        char* Ah = (char*)smem + SA_OFF + nb * A_TILE;
        const int tb  = (n & 1) * 64;
        const int lin = byy * 36 + lid;
        const int m   = byy * 32 + lid;
        const uint32_t mx = (uint32_t)(m & 7) << 4;
#pragma unroll
        for (int j = 0; j < 8; ++j) {
            int k0 = bkq * 16 + 2 * j;
            float v0 = xs[tapoff[tb + k0]     + lin];
            float v1 = xs[tapoff[tb + k0 + 1] + lin];
            __half h0 = __float2half_rn(v0);
            __half h1 = __float2half_rn(v1);
            uint32_t hp = (uint32_t)__half_as_ushort(h0) |
                          ((uint32_t)__half_as_ushort(h1) << 16);
            *(uint32_t*)(Ah + (((uint32_t)(m * 128 + k0 * 2)) ^ mx)) = hp;
        }
    };

    // lane-invariant ldmatrix offsets
    const uint32_t aLane  = (uint32_t)((lid & 15) * 128 + ((lid & 16) ? 16 : 0));
    const uint32_t bLane4 = (uint32_t)((((lid & 7) + ((lid & 16) ? 8 : 0)) * 128) +
                                       ((lid & 8) ? 16 : 0));
    const uint32_t bLane2 = (uint32_t)((lid & 7) * 128 + ((lid & 8) ? 16 : 0));

    float acc[11][4];
#pragma unroll
    for (int ni = 0; ni < 11; ++ni)
#pragma unroll
        for (int r = 0; r < 4; ++r) acc[ni][r] = 0.f;

    // ---- prologue ----
    stage_B(0, 0);
    stage_x(0);
    CPC(); CPW0();
    __syncthreads();
    build_A(0, 0);
    __syncthreads();

    for (int c = 0; c < NCHUNK_; ++c) {
        const int bsel = c & 1;
        if (c + 1 < NCHUNK_) {
            stage_B(c + 1, bsel ^ 1);
            if (((c + 1) & 1) == 0) stage_x((c + 1) >> 1);
            CPC();
        }

        const uint32_t AhB = smb + SA_OFF + bsel * A_TILE;
        const uint32_t BhB = smb + SB_OFF + bsel * (2 * B_TILE);
        const uint32_t BlB = BhB + B_TILE;

#pragma unroll
        for (int ks = 0; ks < 4; ++ks) {
            const uint32_t kso = (uint32_t)ks * 32;
            uint32_t ah[4];
            LDM4(ah, AhB + swz((uint32_t)(m0 * 128) + kso + aLane));
#pragma unroll
            for (int nip = 0; nip < 5; ++nip) {
                const uint32_t bo =
                    swz((uint32_t)((n0 + nip * 16) * 128) + kso + bLane4);
                uint32_t bh[4], bl[4];
                LDM4(bh, BhB + bo);
                LDM4(bl, BlB + bo);
                MMAF16(acc[nip * 2],     ah, bh[0], bh[1]);
                MMAF16(acc[nip * 2 + 1], ah, bh[2], bh[3]);
                MMAF16(acc[nip * 2],     ah, bl[0], bl[1]);
                MMAF16(acc[nip * 2 + 1], ah, bl[2], bl[3]);
            }
            {   // n-group 10 (cols 80..87)
                const uint32_t bo =
                    swz((uint32_t)((n0 + 80) * 128) + kso + bLane2);
                uint32_t bh[2], bl[2];
                LDM2(bh, BhB + bo);
                LDM2(bl, BlB + bo);
                MMAF16(acc[10], ah, bh[0], bh[1]);
                MMAF16(acc[10], ah, bl[0], bl[1]);
            }
        }

        if (c + 1 < NCHUNK_) {
            CPW0();
            __syncthreads();
            build_A(c + 1, bsel ^ 1);
        }
        __syncthreads();
    }

    // ---- epilogue: accums -> smem, sigmoid gates, gated write to g_z ----
    float* sD = (float*)smem;   // [176][132] floats = 92928B, reuses tile smem
#pragma unroll
    for (int ni = 0; ni < 11; ++ni)
#pragma unroll
        for (int r = 0; r < 4; ++r) {
            int m  = m0 + (lid >> 2) + ((r & 2) ? 8 : 0);
            int cc = n0 + ni * 8 + (lid & 3) * 2 + (r & 1);
            sD[cc * 132 + m] = acc[ni][r];
        }
    __syncthreads();

    for (int i = tid; i < 32 * 128; i += NT_) {
        int gi = i >> 7, mm = i & 127;
        int ad = (144 + gi) * 132 + mm;
        sD[ad] = 1.f / (1.f + expf(-(sD[ad] + sG[gi])));
    }
    __syncthreads();

    float* zb = g_z + (size_t)b * NCH_ * NSP_ + (size_t)z0 * 1024 + y0 * 32;
    for (int i = tid; i < 144 * 128; i += NT_) {
        int cc = i >> 7, mm = i & 127;
        float v = sD[cc * 132 + mm];
        float o;
        if (cc < 16) o = fmaxf(v + sS[cc], 0.f);
        else {
            int gi = (cc < 64) ? (cc - 16) / 3 : 16 + (cc - 64) / 5;
            o = v * sD[(144 + gi) * 132 + mm];
        }
        zb[(size_t)cc * NSP_ + mm] = o;
    }
}

// ---------------------------------------------------------------------------
// Depthwise 5^3 gaussian, stride2, pad2 -> (16,16,16). grid (8, 144, 4).
// ---------------------------------------------------------------------------
__global__ __launch_bounds__(256)
void lowpass_kernel(float* __restrict__ out)
{
    const int zt = blockIdx.x;
    const int c  = blockIdx.y;
    const int b  = blockIdx.z;
    const int tid = threadIdx.x;

    __shared__ float sZ[7 * 35 * 35];
    __shared__ float sWg[125];

    if (tid < 125) {
        int kw = tid % 5, t = tid / 5;
        int kh = t % 5,  kd = t / 5;
        double g[5], s = 0.0;
#pragma unroll
        for (int r = 0; r < 5; ++r) {
            double d = (double)(r - 2);
            g[r] = exp(-d * d / 1.5);
            s += g[r];
        }
        sWg[tid] = (float)(g[kd] * g[kh] * g[kw] / (s * s * s));
    }

    const int zo0 = 2 * zt;
    const int zi0 = 2 * zo0 - 2;
    const float* zc = g_z + (size_t)(b * NCH_ + c) * NSP_;

    for (int i = tid; i < 7 * 35 * 35; i += 256) {
        int xi = i % 35;
        int t  = i / 35;
        int yi = t % 35;
        int zi = t / 35;
        int gx = xi - 2, gy = yi - 2, gz = zi0 + zi;
        float v = 0.f;
        if ((unsigned)gx < 32u && (unsigned)gy < 32u && (unsigned)gz < 32u)
            v = zc[(gz * 32 + gy) * 32 + gx];
        sZ[i] = v;
    }
    __syncthreads();

    const int xo = tid & 15;
    const int yo = tid >> 4;
#pragma unroll
    for (int dz = 0; dz < 2; ++dz) {
        float sum = 0.f;
#pragma unroll
        for (int kd = 0; kd < 5; ++kd)
#pragma unroll
            for (int kh = 0; kh < 5; ++kh)
#pragma unroll
                for (int kw = 0; kw < 5; ++kw)
                    sum += sWg[(kd * 5 + kh) * 5 + kw] *
                           sZ[((2 * dz + kd) * 35 + (2 * yo + kh)) * 35 +
                              2 * xo + kw];
        out[((size_t)(b * NCH_ + c) * 16 + (zo0 + dz)) * 256 + yo * 16 + xo] = sum;
    }
}

// ---------------------------------------------------------------------------
extern "C" void kernel_launch(void* const* d_in, const int* in_sizes, int n_in,
                              void* d_out, int out_size)
{
    const float* x  = (const float*)d_in[0];   // (4,72,32,32,32)
    const float* W  = (const float*)d_in[1];   // (176,72,5,5,5)
    const float* sb = (const float*)d_in[2];   // (16,)
    const float* gb = (const float*)d_in[3];   // (32,)
    float* out = (float*)d_out;                // (4,144,16,16,16)

    cudaFuncSetAttribute(conv_mma_kernel,
                         cudaFuncAttributeMaxDynamicSharedMemorySize, SMEM_TOTAL);

    prep_kernel<<<6336, 256>>>(W);
    conv_mma_kernel<<<dim3(8, 32, B_), NT_, SMEM_TOTAL>>>(x, sb, gb);
    lowpass_kernel<<<dim3(8, NCH_, B_), 256>>>(out);
}

// round 8
// speedup vs baseline: 2.9817x; 1.4685x over previous
#include <cuda_runtime.h>
#include <cuda_fp16.h>
#include <math.h>
#include <stdint.h>

// ---------------------------------------------------------------------------
// GatedBlock via mma.sync fp16 implicit GEMM (single-term):
//   D = x_f16 * w_f16  (both quantizations incoherent over K=9216,
//   measured-model rel_err ~2-3e-4, threshold 1e-3)
//   conv3d(72->176, k5, pad2)  ==>  D[M=128 spatial, N=176 co], K = 72*128
//   gate fused into the GEMM epilogue, then depthwise gaussian stride-2.
// ---------------------------------------------------------------------------

#define B_      4
#define CI_     72
#define CO_     176
#define NSP_    (32*32*32)
#define NCH_    144

#define KC_     64            // K per chunk
#define NCHUNK_ 144           // 72*128 / 64
#define A_TILE  16384         // 128 rows x 64 fp16
#define B_TILE  22528         // 176 rows x 64 fp16
#define NT_     512

__device__ float g_z[(size_t)B_ * NCH_ * NSP_];
__device__ __half g_wprep[(size_t)NCHUNK_ * CO_ * KC_];  // fp16, pre-swizzled

// ---- smem byte offsets (dynamic smem) ----
// [0, 92928) is reused by the epilogue sD[176][132]; persistent data above it.
#define SA_OFF    0                        // A: 2 x 16384 = 32768
#define SB_OFF    32768                    // B: 2 x 22528 -> 77824
#define SX_OFF    92928                    // xs: 1584 floats -> 99264
#define XS_FLOATS 1584
#define ST_OFF    99264                    // tapoff: 128 ints -> 99776
#define SSB_OFF   99776
#define SGB_OFF   99840
#define SMEM_TOTAL 99968

// ---------------- helpers ----------------
__device__ __forceinline__ uint32_t smem_u32(const void* p){
    uint32_t a;
    asm("{ .reg .u64 t; cvta.to.shared.u64 t, %1; cvt.u32.u64 %0, t; }"
        : "=r"(a) : "l"(p));
    return a;
}
__device__ __forceinline__ uint32_t swz(uint32_t o){
    return o ^ (((o >> 7) & 7u) << 4);
}

#define CPA16(d,s) asm volatile("cp.async.cg.shared.global [%0], [%1], 16;" :: "r"(d), "l"(s))
#define CPA8(d,s)  asm volatile("cp.async.ca.shared.global [%0], [%1], 8;"  :: "r"(d), "l"(s))
#define CPC()      asm volatile("cp.async.commit_group;")
#define CPW0()     asm volatile("cp.async.wait_group 0;")

#define LDM4(r, a) \
    asm volatile("ldmatrix.sync.aligned.m8n8.x4.shared.b16 {%0,%1,%2,%3}, [%4];" \
        : "=r"((r)[0]),"=r"((r)[1]),"=r"((r)[2]),"=r"((r)[3]) : "r"(a))
#define LDM2(r, a) \
    asm volatile("ldmatrix.sync.aligned.m8n8.x2.shared.b16 {%0,%1}, [%2];" \
        : "=r"((r)[0]),"=r"((r)[1]) : "r"(a))

#define MMAF16(d, a, b0v, b1v) \
    asm volatile("mma.sync.aligned.m16n8k16.row.col.f32.f16.f16.f32 " \
        "{%0,%1,%2,%3}, {%4,%5,%6,%7}, {%8,%9}, {%0,%1,%2,%3};" \
        : "+f"((d)[0]),"+f"((d)[1]),"+f"((d)[2]),"+f"((d)[3]) \
        : "r"((a)[0]),"r"((a)[1]),"r"((a)[2]),"r"((a)[3]), "r"(b0v), "r"(b1v))

// ---------------------------------------------------------------------------
// Weight prep: reorder to K=(ci*128+tap), fp16, pre-apply the XOR swizzle
// so the main kernel can cp.async the tiles linearly.
// ---------------------------------------------------------------------------
__global__ void prep_kernel(const float* __restrict__ W)
{
    int e = blockIdx.x * 256 + threadIdx.x;   // 144*176*64 = 1,622,016 exact
    int col   = e & 63;
    int row   = (e >> 6) % CO_;
    int chunk = e / (CO_ * KC_);
    int k  = chunk * KC_ + col;
    int ci = k >> 7;
    int tap = k & 127;
    float v = (tap < 125) ? W[((size_t)row * CI_ + ci) * 125 + tap] : 0.f;
    uint32_t off = (uint32_t)(row * 128 + col * 2);
    uint32_t sw  = off ^ ((uint32_t)(row & 7) << 4);
    g_wprep[(size_t)chunk * (CO_ * KC_) + (sw >> 1)] = __float2half_rn(v);
}

// ---------------------------------------------------------------------------
// Main kernel: implicit GEMM + fused gate epilogue.
// grid (8 y-tiles, 32 z, 4 b), 512 threads. warps: 8M x 2N, warp tile 16x88.
// ---------------------------------------------------------------------------
__global__ __launch_bounds__(NT_, 1)
void conv_mma_kernel(const float* __restrict__ x,
                     const float* __restrict__ sbg, const float* __restrict__ gbg)
{
    extern __shared__ unsigned char smem[];
    const uint32_t smb = smem_u32(smem);

    const int tid = threadIdx.x;
    const int wid = tid >> 5;
    const int lid = tid & 31;
    const int b  = blockIdx.z;
    const int z0 = blockIdx.y;
    const int y0 = blockIdx.x * 4;

    // builder role: 16 warps = 4 y-groups x 4 k-quarters
    const int byy = wid & 3, bkq = wid >> 2;
    // mma role: 8 M-groups x 2 N-halves
    const int m0 = (wid >> 1) * 16;
    const int n0 = (wid & 1) * 88;

    float* xs     = (float*)(smem + SX_OFF);
    int*   tapoff = (int*)(smem + ST_OFF);
    float* sS     = (float*)(smem + SSB_OFF);
    float* sG     = (float*)(smem + SGB_OFF);

    for (int i = tid; i < XS_FLOATS; i += NT_) xs[i] = 0.f;
    if (tid < 128) {
        int tap = tid;
        int kd = tap / 25, r = tap % 25;
        int kh = r / 5, kw = r % 5;
        tapoff[tid] = (tap < 125) ? (kd * 8 + kh) * 36 + kw : 1440;
    }
    if (tid < 16) sS[tid] = sbg[tid];
    if (tid < 32) sG[tid] = gbg[tid];
    __syncthreads();

    const float* xb = x + (size_t)b * CI_ * NSP_;

    auto stage_x = [&](int ci) {
        const float* xc = xb + (size_t)ci * NSP_;
        for (int it = tid; it < 640; it += NT_) {
            int ck = it & 15;
            int row = it >> 4;           // zi*8 + yi
            int yi = row & 7, zi = row >> 3;
            int gy = y0 + yi - 2, gz = z0 + zi - 2;
            if ((unsigned)gy < 32u && (unsigned)gz < 32u)
                CPA8(smb + SX_OFF + (uint32_t)(row * 36 + 2 + ck * 2) * 4,
                     xc + ((gz * 32 + gy) * 32 + ck * 2));
        }
    };
    auto stage_B = [&](int n, int nb) {
        const char* src = (const char*)g_wprep + (size_t)n * B_TILE;
        uint32_t dst = smb + SB_OFF + nb * B_TILE;
        for (int i = tid; i < B_TILE / 16; i += NT_)
            CPA16(dst + i * 16, src + i * 16);
    };
    auto build_A = [&](int n, int nb) {
        char* Ah = (char*)smem + SA_OFF + nb * A_TILE;
        const int tb  = (n & 1) * 64;
        const int lin = byy * 36 + lid;
        const int m   = byy * 32 + lid;
        const uint32_t mx = (uint32_t)(m & 7) << 4;
#pragma unroll
        for (int j = 0; j < 8; ++j) {
            int k0 = bkq * 16 + 2 * j;
            float v0 = xs[tapoff[tb + k0]     + lin];
            float v1 = xs[tapoff[tb + k0 + 1] + lin];
            __half h0 = __float2half_rn(v0);
            __half h1 = __float2half_rn(v1);
            uint32_t hp = (uint32_t)__half_as_ushort(h0) |
                          ((uint32_t)__half_as_ushort(h1) << 16);
            *(uint32_t*)(Ah + (((uint32_t)(m * 128 + k0 * 2)) ^ mx)) = hp;
        }
    };

    // lane-invariant ldmatrix offsets
    const uint32_t aLane  = (uint32_t)((lid & 15) * 128 + ((lid & 16) ? 16 : 0));
    const uint32_t bLane4 = (uint32_t)((((lid & 7) + ((lid & 16) ? 8 : 0)) * 128) +
                                       ((lid & 8) ? 16 : 0));
    const uint32_t bLane2 = (uint32_t)((lid & 7) * 128 + ((lid & 8) ? 16 : 0));

    float acc[11][4];
#pragma unroll
    for (int ni = 0; ni < 11; ++ni)
#pragma unroll
        for (int r = 0; r < 4; ++r) acc[ni][r] = 0.f;

    // ---- prologue ----
    stage_B(0, 0);
    stage_x(0);
    CPC(); CPW0();
    __syncthreads();
    build_A(0, 0);
    __syncthreads();

    for (int c = 0; c < NCHUNK_; ++c) {
        const int bsel = c & 1;
        if (c + 1 < NCHUNK_) {
            stage_B(c + 1, bsel ^ 1);
            if (((c + 1) & 1) == 0) stage_x((c + 1) >> 1);
            CPC();
        }

        const uint32_t AhB = smb + SA_OFF + bsel * A_TILE;
        const uint32_t BhB = smb + SB_OFF + bsel * B_TILE;

#pragma unroll
        for (int ks = 0; ks < 4; ++ks) {
            const uint32_t kso = (uint32_t)ks * 32;
            uint32_t ah[4];
            LDM4(ah, AhB + swz((uint32_t)(m0 * 128) + kso + aLane));
#pragma unroll
            for (int nip = 0; nip < 5; ++nip) {
                uint32_t bh[4];
                LDM4(bh, BhB + swz((uint32_t)((n0 + nip * 16) * 128) + kso + bLane4));
                MMAF16(acc[nip * 2],     ah, bh[0], bh[1]);
                MMAF16(acc[nip * 2 + 1], ah, bh[2], bh[3]);
            }
            {   // n-group 10 (cols 80..87)
                uint32_t b2[2];
                LDM2(b2, BhB + swz((uint32_t)((n0 + 80) * 128) + kso + bLane2));
                MMAF16(acc[10], ah, b2[0], b2[1]);
            }
        }

        if (c + 1 < NCHUNK_) {
            CPW0();
            __syncthreads();
            build_A(c + 1, bsel ^ 1);
        }
        __syncthreads();
    }

    // ---- epilogue: accums -> smem, sigmoid gates, gated write to g_z ----
    float* sD = (float*)smem;   // [176][132] floats = 92928B, reuses tile smem
#pragma unroll
    for (int ni = 0; ni < 11; ++ni)
#pragma unroll
        for (int r = 0; r < 4; ++r) {
            int m  = m0 + (lid >> 2) + ((r & 2) ? 8 : 0);
            int cc = n0 + ni * 8 + (lid & 3) * 2 + (r & 1);
            sD[cc * 132 + m] = acc[ni][r];
        }
    __syncthreads();

    for (int i = tid; i < 32 * 128; i += NT_) {
        int gi = i >> 7, mm = i & 127;
        int ad = (144 + gi) * 132 + mm;
        sD[ad] = 1.f / (1.f + expf(-(sD[ad] + sG[gi])));
    }
    __syncthreads();

    float* zb = g_z + (size_t)b * NCH_ * NSP_ + (size_t)z0 * 1024 + y0 * 32;
    for (int i = tid; i < 144 * 128; i += NT_) {
        int cc = i >> 7, mm = i & 127;
        float v = sD[cc * 132 + mm];
        float o;
        if (cc < 16) o = fmaxf(v + sS[cc], 0.f);
        else {
            int gi = (cc < 64) ? (cc - 16) / 3 : 16 + (cc - 64) / 5;
            o = v * sD[(144 + gi) * 132 + mm];
        }
        zb[(size_t)cc * NSP_ + mm] = o;
    }
}

// ---------------------------------------------------------------------------
// Depthwise 5^3 gaussian, stride2, pad2 -> (16,16,16). grid (8, 144, 4).
// ---------------------------------------------------------------------------
__global__ __launch_bounds__(256)
void lowpass_kernel(float* __restrict__ out)
{
    const int zt = blockIdx.x;
    const int c  = blockIdx.y;
    const int b  = blockIdx.z;
    const int tid = threadIdx.x;

    __shared__ float sZ[7 * 35 * 35];
    __shared__ float sWg[125];

    if (tid < 125) {
        int kw = tid % 5, t = tid / 5;
        int kh = t % 5,  kd = t / 5;
        double g[5], s = 0.0;
#pragma unroll
        for (int r = 0; r < 5; ++r) {
            double d = (double)(r - 2);
            g[r] = exp(-d * d / 1.5);
            s += g[r];
        }
        sWg[tid] = (float)(g[kd] * g[kh] * g[kw] / (s * s * s));
    }

    const int zo0 = 2 * zt;
    const int zi0 = 2 * zo0 - 2;
    const float* zc = g_z + (size_t)(b * NCH_ + c) * NSP_;

    for (int i = tid; i < 7 * 35 * 35; i += 256) {
        int xi = i % 35;
        int t  = i / 35;
        int yi = t % 35;
        int zi = t / 35;
        int gx = xi - 2, gy = yi - 2, gz = zi0 + zi;
        float v = 0.f;
        if ((unsigned)gx < 32u && (unsigned)gy < 32u && (unsigned)gz < 32u)
            v = zc[(gz * 32 + gy) * 32 + gx];
        sZ[i] = v;
    }
    __syncthreads();

    const int xo = tid & 15;
    const int yo = tid >> 4;
#pragma unroll
    for (int dz = 0; dz < 2; ++dz) {
        float sum = 0.f;
#pragma unroll
        for (int kd = 0; kd < 5; ++kd)
#pragma unroll
            for (int kh = 0; kh < 5; ++kh)
#pragma unroll
                for (int kw = 0; kw < 5; ++kw)
                    sum += sWg[(kd * 5 + kh) * 5 + kw] *
                           sZ[((2 * dz + kd) * 35 + (2 * yo + kh)) * 35 +
                              2 * xo + kw];
        out[((size_t)(b * NCH_ + c) * 16 + (zo0 + dz)) * 256 + yo * 16 + xo] = sum;
    }
}

// ---------------------------------------------------------------------------
extern "C" void kernel_launch(void* const* d_in, const int* in_sizes, int n_in,
                              void* d_out, int out_size)
{
    const float* x  = (const float*)d_in[0];   // (4,72,32,32,32)
    const float* W  = (const float*)d_in[1];   // (176,72,5,5,5)
    const float* sb = (const float*)d_in[2];   // (16,)
    const float* gb = (const float*)d_in[3];   // (32,)
    float* out = (float*)d_out;                // (4,144,16,16,16)

    cudaFuncSetAttribute(conv_mma_kernel,
                         cudaFuncAttributeMaxDynamicSharedMemorySize, SMEM_TOTAL);

    prep_kernel<<<6336, 256>>>(W);
    conv_mma_kernel<<<dim3(8, 32, B_), NT_, SMEM_TOTAL>>>(x, sb, gb);
    lowpass_kernel<<<dim3(8, NCH_, B_), 256>>>(out);
}

// round 9
// speedup vs baseline: 3.1297x; 1.0496x over previous
#include <cuda_runtime.h>
#include <cuda_fp16.h>
#include <math.h>
#include <stdint.h>

// ---------------------------------------------------------------------------
// GatedBlock via mma.sync fp16 implicit GEMM (single-term):
//   D = x_f16 * w_f16 ;  conv3d(72->176,k5,pad2) => D[M=128, N=176], K=72*128
//   gate fused into the GEMM epilogue, then depthwise gaussian stride-2.
// Round 9: KC=128 (one ci per chunk), tiles stored as two stacked 64-k halves
//   so the proven 128B-row swizzle + ldmatrix addressing is unchanged.
// ---------------------------------------------------------------------------

#define B_      4
#define CI_     72
#define CO_     176
#define NSP_    (32*32*32)
#define NCH_    144

#define NCHUNK_ 72            // one input channel per chunk (K=128)
#define A_HALF  16384         // 128 rows x 64 fp16
#define A_TILE  (2*A_HALF)    // [khalf][128][64]
#define B_HALF  22528         // 176 rows x 64 fp16
#define B_TILE  (2*B_HALF)    // [khalf][176][64]
#define NT_     512

__device__ float g_z[(size_t)B_ * NCH_ * NSP_];
__device__ __half g_wprep[(size_t)NCHUNK_ * CO_ * 128];  // fp16, pre-swizzled

// ---- smem byte offsets (dynamic smem) ----
// [0, 92928) is reused by the epilogue sD[176][132]; persistent data above it.
#define SA_OFF    0                        // A: 2 x 32768 = 65536
#define SB_OFF    65536                    // B: 2 x 45056 -> 155648
#define SX_OFF    155648                   // xs: 1584 floats -> 161984
#define XS_FLOATS 1584
#define ST_OFF    161984                   // tapoff: 128 ints -> 162496
#define SSB_OFF   162496
#define SGB_OFF   162560
#define SMEM_TOTAL 162688

// ---------------- helpers ----------------
__device__ __forceinline__ uint32_t smem_u32(const void* p){
    uint32_t a;
    asm("{ .reg .u64 t; cvta.to.shared.u64 t, %1; cvt.u32.u64 %0, t; }"
        : "=r"(a) : "l"(p));
    return a;
}
__device__ __forceinline__ uint32_t swz(uint32_t o){
    return o ^ (((o >> 7) & 7u) << 4);
}

#define CPA16(d,s) asm volatile("cp.async.cg.shared.global [%0], [%1], 16;" :: "r"(d), "l"(s))
#define CPA8(d,s)  asm volatile("cp.async.ca.shared.global [%0], [%1], 8;"  :: "r"(d), "l"(s))
#define CPC()      asm volatile("cp.async.commit_group;")
#define CPW0()     asm volatile("cp.async.wait_group 0;")

#define LDM4(r, a) \
    asm volatile("ldmatrix.sync.aligned.m8n8.x4.shared.b16 {%0,%1,%2,%3}, [%4];" \
        : "=r"((r)[0]),"=r"((r)[1]),"=r"((r)[2]),"=r"((r)[3]) : "r"(a))
#define LDM2(r, a) \
    asm volatile("ldmatrix.sync.aligned.m8n8.x2.shared.b16 {%0,%1}, [%2];" \
        : "=r"((r)[0]),"=r"((r)[1]) : "r"(a))

#define MMAF16(d, a, b0v, b1v) \
    asm volatile("mma.sync.aligned.m16n8k16.row.col.f32.f16.f16.f32 " \
        "{%0,%1,%2,%3}, {%4,%5,%6,%7}, {%8,%9}, {%0,%1,%2,%3};" \
        : "+f"((d)[0]),"+f"((d)[1]),"+f"((d)[2]),"+f"((d)[3]) \
        : "r"((a)[0]),"r"((a)[1]),"r"((a)[2]),"r"((a)[3]), "r"(b0v), "r"(b1v))

// ---------------------------------------------------------------------------
// Weight prep: chunk = ci; tap = k (0..127, >=125 zero). Tile = [khalf][176][64]
// fp16 with the 128B-row XOR swizzle pre-applied (cp.async'd linearly later).
// ---------------------------------------------------------------------------
__global__ void prep_kernel(const float* __restrict__ W)
{
    int e = blockIdx.x * 256 + threadIdx.x;   // 72*176*128 = 1,622,016 exact
    int col   = e & 127;                      // k within chunk
    int row   = (e >> 7) % CO_;
    int chunk = e / (CO_ * 128);
    float v = (col < 125) ? W[((size_t)row * CI_ + chunk) * 125 + col] : 0.f;
    int khalf = col >> 6, c6 = col & 63;
    uint32_t off = (uint32_t)(row * 128 + c6 * 2);
    uint32_t sw  = off ^ ((uint32_t)(row & 7) << 4);
    g_wprep[(size_t)chunk * (CO_ * 128) + (size_t)khalf * (CO_ * 64) + (sw >> 1)]
        = __float2half_rn(v);
}

// ---------------------------------------------------------------------------
// Main kernel: implicit GEMM + fused gate epilogue.
// grid (8 y-tiles, 32 z, 4 b), 512 threads. warps: 8M x 2N, warp tile 16x88.
// ---------------------------------------------------------------------------
__global__ __launch_bounds__(NT_, 1)
void conv_mma_kernel(const float* __restrict__ x,
                     const float* __restrict__ sbg, const float* __restrict__ gbg)
{
    extern __shared__ unsigned char smem[];
    const uint32_t smb = smem_u32(smem);

    const int tid = threadIdx.x;
    const int wid = tid >> 5;
    const int lid = tid & 31;
    const int b  = blockIdx.z;
    const int z0 = blockIdx.y;
    const int y0 = blockIdx.x * 4;

    // builder role: 16 warps = 4 y-groups x 4 k-quarters (32 k each)
    const int byy = wid & 3, bkq = wid >> 2;
    // mma role: 8 M-groups x 2 N-halves
    const int m0 = (wid >> 1) * 16;
    const int n0 = (wid & 1) * 88;

    float* xs     = (float*)(smem + SX_OFF);
    int*   tapoff = (int*)(smem + ST_OFF);
    float* sS     = (float*)(smem + SSB_OFF);
    float* sG     = (float*)(smem + SGB_OFF);

    for (int i = tid; i < XS_FLOATS; i += NT_) xs[i] = 0.f;
    if (tid < 128) {
        int tap = tid;
        int kd = tap / 25, r = tap % 25;
        int kh = r / 5, kw = r % 5;
        tapoff[tid] = (tap < 125) ? (kd * 8 + kh) * 36 + kw : 1440;
    }
    if (tid < 16) sS[tid] = sbg[tid];
    if (tid < 32) sG[tid] = gbg[tid];
    __syncthreads();

    const float* xb = x + (size_t)b * CI_ * NSP_;

    auto stage_x = [&](int ci) {
        const float* xc = xb + (size_t)ci * NSP_;
        for (int it = tid; it < 640; it += NT_) {
            int ck = it & 15;
            int row = it >> 4;           // zi*8 + yi
            int yi = row & 7, zi = row >> 3;
            int gy = y0 + yi - 2, gz = z0 + zi - 2;
            if ((unsigned)gy < 32u && (unsigned)gz < 32u)
                CPA8(smb + SX_OFF + (uint32_t)(row * 36 + 2 + ck * 2) * 4,
                     xc + ((gz * 32 + gy) * 32 + ck * 2));
        }
    };
    auto stage_B = [&](int n, int nb) {
        const char* src = (const char*)g_wprep + (size_t)n * B_TILE;
        uint32_t dst = smb + SB_OFF + nb * B_TILE;
        for (int i = tid; i < B_TILE / 16; i += NT_)
            CPA16(dst + i * 16, src + i * 16);
    };
    auto build_A = [&](int nb) {
        char* Abase = (char*)smem + SA_OFF + nb * A_TILE;
        const int lin = byy * 36 + lid;
        const int m   = byy * 32 + lid;
        const uint32_t mx = (uint32_t)(m & 7) << 4;
#pragma unroll
        for (int j = 0; j < 16; ++j) {
            int k0 = bkq * 32 + 2 * j;
            float v0 = xs[tapoff[k0]     + lin];
            float v1 = xs[tapoff[k0 + 1] + lin];
            __half h0 = __float2half_rn(v0);
            __half h1 = __float2half_rn(v1);
            uint32_t hp = (uint32_t)__half_as_ushort(h0) |
                          ((uint32_t)__half_as_ushort(h1) << 16);
            int khalf = k0 >> 6, c6 = k0 & 63;
            *(uint32_t*)(Abase + khalf * A_HALF +
                         (((uint32_t)(m * 128 + c6 * 2)) ^ mx)) = hp;
        }
    };

    // lane-invariant ldmatrix offsets
    const uint32_t aLane  = (uint32_t)((lid & 15) * 128 + ((lid & 16) ? 16 : 0));
    const uint32_t bLane4 = (uint32_t)((((lid & 7) + ((lid & 16) ? 8 : 0)) * 128) +
                                       ((lid & 8) ? 16 : 0));
    const uint32_t bLane2 = (uint32_t)((lid & 7) * 128 + ((lid & 8) ? 16 : 0));

    float acc[11][4];
#pragma unroll
    for (int ni = 0; ni < 11; ++ni)
#pragma unroll
        for (int r = 0; r < 4; ++r) acc[ni][r] = 0.f;

    // ---- prologue ----
    stage_B(0, 0);
    stage_x(0);
    CPC(); CPW0();
    __syncthreads();
    build_A(0);
    __syncthreads();

    for (int c = 0; c < NCHUNK_; ++c) {
        const int bsel = c & 1;
        if (c + 1 < NCHUNK_) {
            stage_B(c + 1, bsel ^ 1);
            stage_x(c + 1);
            CPC();
        }

        const uint32_t AB = smb + SA_OFF + bsel * A_TILE;
        const uint32_t BB = smb + SB_OFF + bsel * B_TILE;

#pragma unroll
        for (int ks = 0; ks < 8; ++ks) {
            const uint32_t Ah = AB + (ks >> 2) * A_HALF;
            const uint32_t Bh = BB + (ks >> 2) * B_HALF;
            const uint32_t kso = (uint32_t)(ks & 3) * 32;
            uint32_t ah[4];
            LDM4(ah, Ah + swz((uint32_t)(m0 * 128) + kso + aLane));
#pragma unroll
            for (int nip = 0; nip < 5; ++nip) {
                uint32_t bh[4];
                LDM4(bh, Bh + swz((uint32_t)((n0 + nip * 16) * 128) + kso + bLane4));
                MMAF16(acc[nip * 2],     ah, bh[0], bh[1]);
                MMAF16(acc[nip * 2 + 1], ah, bh[2], bh[3]);
            }
            {   // n-group 10 (cols 80..87)
                uint32_t b2[2];
                LDM2(b2, Bh + swz((uint32_t)((n0 + 80) * 128) + kso + bLane2));
                MMAF16(acc[10], ah, b2[0], b2[1]);
            }
        }

        if (c + 1 < NCHUNK_) {
            CPW0();
            __syncthreads();
            build_A(bsel ^ 1);
        }
        __syncthreads();
    }

    // ---- epilogue: accums -> smem, sigmoid gates, gated write to g_z ----
    float* sD = (float*)smem;   // [176][132] floats = 92928B, reuses tile smem
#pragma unroll
    for (int ni = 0; ni < 11; ++ni)
#pragma unroll
        for (int r = 0; r < 4; ++r) {
            int m  = m0 + (lid >> 2) + ((r & 2) ? 8 : 0);
            int cc = n0 + ni * 8 + (lid & 3) * 2 + (r & 1);
            sD[cc * 132 + m] = acc[ni][r];
        }
    __syncthreads();

    for (int i = tid; i < 32 * 128; i += NT_) {
        int gi = i >> 7, mm = i & 127;
        int ad = (144 + gi) * 132 + mm;
        sD[ad] = 1.f / (1.f + expf(-(sD[ad] + sG[gi])));
    }
    __syncthreads();

    float* zb = g_z + (size_t)b * NCH_ * NSP_ + (size_t)z0 * 1024 + y0 * 32;
    for (int i = tid; i < 144 * 128; i += NT_) {
        int cc = i >> 7, mm = i & 127;
        float v = sD[cc * 132 + mm];
        float o;
        if (cc < 16) o = fmaxf(v + sS[cc], 0.f);
        else {
            int gi = (cc < 64) ? (cc - 16) / 3 : 16 + (cc - 64) / 5;
            o = v * sD[(144 + gi) * 132 + mm];
        }
        zb[(size_t)cc * NSP_ + mm] = o;
    }
}

// ---------------------------------------------------------------------------
// Depthwise 5^3 gaussian, stride2, pad2 -> (16,16,16). grid (8, 144, 4).
// ---------------------------------------------------------------------------
__global__ __launch_bounds__(256)
void lowpass_kernel(float* __restrict__ out)
{
    const int zt = blockIdx.x;
    const int c  = blockIdx.y;
    const int b  = blockIdx.z;
    const int tid = threadIdx.x;

    __shared__ float sZ[7 * 35 * 35];
    __shared__ float sWg[125];

    if (tid < 125) {
        int kw = tid % 5, t = tid / 5;
        int kh = t % 5,  kd = t / 5;
        double g[5], s = 0.0;
#pragma unroll
        for (int r = 0; r < 5; ++r) {
            double d = (double)(r - 2);
            g[r] = exp(-d * d / 1.5);
            s += g[r];
        }
        sWg[tid] = (float)(g[kd] * g[kh] * g[kw] / (s * s * s));
    }

    const int zo0 = 2 * zt;
    const int zi0 = 2 * zo0 - 2;
    const float* zc = g_z + (size_t)(b * NCH_ + c) * NSP_;

    for (int i = tid; i < 7 * 35 * 35; i += 256) {
        int xi = i % 35;
        int t  = i / 35;
        int yi = t % 35;
        int zi = t / 35;
        int gx = xi - 2, gy = yi - 2, gz = zi0 + zi;
        float v = 0.f;
        if ((unsigned)gx < 32u && (unsigned)gy < 32u && (unsigned)gz < 32u)
            v = zc[(gz * 32 + gy) * 32 + gx];
        sZ[i] = v;
    }
    __syncthreads();

    const int xo = tid & 15;
    const int yo = tid >> 4;
#pragma unroll
    for (int dz = 0; dz < 2; ++dz) {
        float sum = 0.f;
#pragma unroll
        for (int kd = 0; kd < 5; ++kd)
#pragma unroll
            for (int kh = 0; kh < 5; ++kh)
#pragma unroll
                for (int kw = 0; kw < 5; ++kw)
                    sum += sWg[(kd * 5 + kh) * 5 + kw] *
                           sZ[((2 * dz + kd) * 35 + (2 * yo + kh)) * 35 +
                              2 * xo + kw];
        out[((size_t)(b * NCH_ + c) * 16 + (zo0 + dz)) * 256 + yo * 16 + xo] = sum;
    }
}

// ---------------------------------------------------------------------------
extern "C" void kernel_launch(void* const* d_in, const int* in_sizes, int n_in,
                              void* d_out, int out_size)
{
    const float* x  = (const float*)d_in[0];   // (4,72,32,32,32)
    const float* W  = (const float*)d_in[1];   // (176,72,5,5,5)
    const float* sb = (const float*)d_in[2];   // (16,)
    const float* gb = (const float*)d_in[3];   // (32,)
    float* out = (float*)d_out;                // (4,144,16,16,16)

    cudaFuncSetAttribute(conv_mma_kernel,
                         cudaFuncAttributeMaxDynamicSharedMemorySize, SMEM_TOTAL);

    prep_kernel<<<6336, 256>>>(W);
    conv_mma_kernel<<<dim3(8, 32, B_), NT_, SMEM_TOTAL>>>(x, sb, gb);
    lowpass_kernel<<<dim3(8, NCH_, B_), 256>>>(out);
}

// round 10
// speedup vs baseline: 3.2484x; 1.0379x over previous
#include <cuda_runtime.h>
#include <cuda_fp16.h>
#include <math.h>
#include <stdint.h>

// ---------------------------------------------------------------------------
// GatedBlock via mma.sync fp16 implicit GEMM (single-term):
//   D = x_f16 * w_f16 ;  conv3d(72->176,k5,pad2) => D[M=128, N=176], K=72*128
//   gate fused into the GEMM epilogue, then depthwise gaussian stride-2.
// Round 10: 4M x 4N warp layout (B re-read 8x -> 4x) + fp16 x image.
// ---------------------------------------------------------------------------

#define B_      4
#define CI_     72
#define CO_     176
#define NSP_    (32*32*32)
#define NCH_    144

#define NCHUNK_ 72            // one input channel per chunk (K=128)
#define A_HALF  16384         // 128 rows x 64 fp16
#define A_TILE  (2*A_HALF)    // [khalf][128][64]
#define B_HALF  22528         // 176 rows x 64 fp16
#define B_TILE  (2*B_HALF)    // [khalf][176][64]
#define NT_     512

__device__ float  g_z[(size_t)B_ * NCH_ * NSP_];
__device__ __half g_wprep[(size_t)NCHUNK_ * CO_ * 128];   // fp16, pre-swizzled
__device__ __half g_xh[(size_t)B_ * CI_ * NSP_];          // fp16 x image

// ---- smem byte offsets (dynamic smem) ----
// [0, 92928) is reused by the epilogue sD[176][132]; persistent data above it.
#define SA_OFF    0                        // A: 2 x 32768 = 65536
#define SB_OFF    65536                    // B: 2 x 45056 -> 155648
#define SX_OFF    155648                   // xs: 1584 halves -> 158816
#define XS_VALS   1584
#define ST_OFF    158848                   // tapoff: 128 ints -> 159360
#define SSB_OFF   159360
#define SGB_OFF   159424
#define SMEM_TOTAL 159552

// ---------------- helpers ----------------
__device__ __forceinline__ uint32_t smem_u32(const void* p){
    uint32_t a;
    asm("{ .reg .u64 t; cvta.to.shared.u64 t, %1; cvt.u32.u64 %0, t; }"
        : "=r"(a) : "l"(p));
    return a;
}
__device__ __forceinline__ uint32_t swz(uint32_t o){
    return o ^ (((o >> 7) & 7u) << 4);
}

#define CPA16(d,s) asm volatile("cp.async.cg.shared.global [%0], [%1], 16;" :: "r"(d), "l"(s))
#define CPA4(d,s)  asm volatile("cp.async.ca.shared.global [%0], [%1], 4;"  :: "r"(d), "l"(s))
#define CPC()      asm volatile("cp.async.commit_group;")
#define CPW0()     asm volatile("cp.async.wait_group 0;")

#define LDM4(r, a) \
    asm volatile("ldmatrix.sync.aligned.m8n8.x4.shared.b16 {%0,%1,%2,%3}, [%4];" \
        : "=r"((r)[0]),"=r"((r)[1]),"=r"((r)[2]),"=r"((r)[3]) : "r"(a))

#define MMAF16(d, a, b0v, b1v) \
    asm volatile("mma.sync.aligned.m16n8k16.row.col.f32.f16.f16.f32 " \
        "{%0,%1,%2,%3}, {%4,%5,%6,%7}, {%8,%9}, {%0,%1,%2,%3};" \
        : "+f"((d)[0]),"+f"((d)[1]),"+f"((d)[2]),"+f"((d)[3]) \
        : "r"((a)[0]),"r"((a)[1]),"r"((a)[2]),"r"((a)[3]), "r"(b0v), "r"(b1v))

// ---------------------------------------------------------------------------
// Weight prep: chunk = ci; tile = [khalf][176][64] fp16, swizzle pre-applied.
// ---------------------------------------------------------------------------
__global__ void prep_kernel(const float* __restrict__ W)
{
    int e = blockIdx.x * 256 + threadIdx.x;   // 72*176*128 = 1,622,016 exact
    int col   = e & 127;
    int row   = (e >> 7) % CO_;
    int chunk = e / (CO_ * 128);
    float v = (col < 125) ? W[((size_t)row * CI_ + chunk) * 125 + col] : 0.f;
    int khalf = col >> 6, c6 = col & 63;
    uint32_t off = (uint32_t)(row * 128 + c6 * 2);
    uint32_t sw  = off ^ ((uint32_t)(row & 7) << 4);
    g_wprep[(size_t)chunk * (CO_ * 128) + (size_t)khalf * (CO_ * 64) + (sw >> 1)]
        = __float2half_rn(v);
}

// x -> fp16 image (numerics identical to converting in the builder)
__global__ void prep_x_kernel(const float* __restrict__ x)
{
    size_t i = (size_t)blockIdx.x * 256 + threadIdx.x;   // 9,437,184 exact
    g_xh[i] = __float2half_rn(x[i]);
}

// ---------------------------------------------------------------------------
// Main kernel: implicit GEMM + fused gate epilogue.
// grid (8 y-tiles, 32 z, 4 b), 512 threads.
// warps: 4M x 4N; warp tile M=32, N = 48/48/48/32.
// ---------------------------------------------------------------------------
__global__ __launch_bounds__(NT_, 1)
void conv_mma_kernel(const float* __restrict__ sbg, const float* __restrict__ gbg)
{
    extern __shared__ unsigned char smem[];
    const uint32_t smb = smem_u32(smem);

    const int tid = threadIdx.x;
    const int wid = tid >> 5;
    const int lid = tid & 31;
    const int b  = blockIdx.z;
    const int z0 = blockIdx.y;
    const int y0 = blockIdx.x * 4;

    // builder role: 16 warps = 4 y-groups x 4 k-quarters (32 k each)
    const int byy = wid & 3, bkq = wid >> 2;
    // mma role: 4 M-groups x 4 N-groups
    const int mw = wid & 3, nw = wid >> 2;
    const int m0 = mw * 32;
    const int n0 = nw * 48;                 // nw=3 -> 144
    const int NG = (nw == 3) ? 4 : 6;       // n8 groups in this warp

    __half* xs    = (__half*)(smem + SX_OFF);
    int*   tapoff = (int*)(smem + ST_OFF);
    float* sS     = (float*)(smem + SSB_OFF);
    float* sG     = (float*)(smem + SGB_OFF);

    for (int i = tid; i < XS_VALS; i += NT_) xs[i] = __ushort_as_half(0);
    if (tid < 128) {
        int tap = tid;
        int kd = tap / 25, r = tap % 25;
        int kh = r / 5, kw = r % 5;
        tapoff[tid] = (tap < 125) ? (kd * 8 + kh) * 36 + kw : 1440;
    }
    if (tid < 16) sS[tid] = sbg[tid];
    if (tid < 32) sG[tid] = gbg[tid];
    __syncthreads();

    const __half* xb = g_xh + (size_t)b * CI_ * NSP_;

    auto stage_x = [&](int ci) {
        const __half* xc = xb + (size_t)ci * NSP_;
        for (int it = tid; it < 640; it += NT_) {
            int ck = it & 15;
            int row = it >> 4;           // zi*8 + yi
            int yi = row & 7, zi = row >> 3;
            int gy = y0 + yi - 2, gz = z0 + zi - 2;
            if ((unsigned)gy < 32u && (unsigned)gz < 32u)
                CPA4(smb + SX_OFF + (uint32_t)(row * 36 + 2 + ck * 2) * 2,
                     xc + ((gz * 32 + gy) * 32 + ck * 2));
        }
    };
    auto stage_B = [&](int n, int nb) {
        const char* src = (const char*)g_wprep + (size_t)n * B_TILE;
        uint32_t dst = smb + SB_OFF + nb * B_TILE;
        for (int i = tid; i < B_TILE / 16; i += NT_)
            CPA16(dst + i * 16, src + i * 16);
    };
    auto build_A = [&](int nb) {
        char* Abase = (char*)smem + SA_OFF + nb * A_TILE;
        const int lin = byy * 36 + lid;
        const int m   = byy * 32 + lid;
        const uint32_t mx = (uint32_t)(m & 7) << 4;
#pragma unroll
        for (int j = 0; j < 16; ++j) {
            int k0 = bkq * 32 + 2 * j;
            uint32_t t0 = *(const unsigned short*)((const char*)xs +
                              (uint32_t)(tapoff[k0]     + lin) * 2);
            uint32_t t1 = *(const unsigned short*)((const char*)xs +
                              (uint32_t)(tapoff[k0 + 1] + lin) * 2);
            uint32_t hp = t0 | (t1 << 16);
            int khalf = k0 >> 6, c6 = k0 & 63;
            *(uint32_t*)(Abase + khalf * A_HALF +
                         (((uint32_t)(m * 128 + c6 * 2)) ^ mx)) = hp;
        }
    };

    // lane-invariant ldmatrix offsets
    const uint32_t aLane  = (uint32_t)((lid & 15) * 128 + ((lid & 16) ? 16 : 0));
    const uint32_t bLane4 = (uint32_t)((((lid & 7) + ((lid & 16) ? 8 : 0)) * 128) +
                                       ((lid & 8) ? 16 : 0));

    float acc[2][6][4];
#pragma unroll
    for (int mi = 0; mi < 2; ++mi)
#pragma unroll
        for (int ni = 0; ni < 6; ++ni)
#pragma unroll
            for (int r = 0; r < 4; ++r) acc[mi][ni][r] = 0.f;

    // ---- prologue ----
    stage_B(0, 0);
    stage_x(0);
    CPC(); CPW0();
    __syncthreads();
    build_A(0);
    __syncthreads();

    for (int c = 0; c < NCHUNK_; ++c) {
        const int bsel = c & 1;
        if (c + 1 < NCHUNK_) {
            stage_B(c + 1, bsel ^ 1);
            stage_x(c + 1);
            CPC();
        }

        const uint32_t AB = smb + SA_OFF + bsel * A_TILE;
        const uint32_t BB = smb + SB_OFF + bsel * B_TILE;

#pragma unroll
        for (int ks = 0; ks < 8; ++ks) {
            const uint32_t Ah = AB + (ks >> 2) * A_HALF;
            const uint32_t Bh = BB + (ks >> 2) * B_HALF;
            const uint32_t kso = (uint32_t)(ks & 3) * 32;
            uint32_t a0[4], a1[4];
            LDM4(a0, Ah + swz((uint32_t)(m0       * 128) + kso + aLane));
            LDM4(a1, Ah + swz((uint32_t)((m0+16)  * 128) + kso + aLane));
#pragma unroll
            for (int g = 0; g < 3; ++g) {
                if (g * 2 >= NG) break;
                uint32_t bh[4];
                LDM4(bh, Bh + swz((uint32_t)((n0 + g * 16) * 128) + kso + bLane4));
                MMAF16(acc[0][g * 2],     a0, bh[0], bh[1]);
                MMAF16(acc[1][g * 2],     a1, bh[0], bh[1]);
                MMAF16(acc[0][g * 2 + 1], a0, bh[2], bh[3]);
                MMAF16(acc[1][g * 2 + 1], a1, bh[2], bh[3]);
            }
        }

        if (c + 1 < NCHUNK_) {
            CPW0();
            __syncthreads();
            build_A(bsel ^ 1);
        }
        __syncthreads();
    }

    // ---- epilogue: accums -> smem, sigmoid gates, gated write to g_z ----
    float* sD = (float*)smem;   // [176][132] floats = 92928B, reuses tile smem
#pragma unroll
    for (int mi = 0; mi < 2; ++mi)
#pragma unroll
        for (int ni = 0; ni < 6; ++ni) {
            if (ni >= NG) break;
#pragma unroll
            for (int r = 0; r < 4; ++r) {
                int m  = m0 + mi * 16 + (lid >> 2) + ((r & 2) ? 8 : 0);
                int cc = n0 + ni * 8 + (lid & 3) * 2 + (r & 1);
                sD[cc * 132 + m] = acc[mi][ni][r];
            }
        }
    __syncthreads();

    for (int i = tid; i < 32 * 128; i += NT_) {
        int gi = i >> 7, mm = i & 127;
        int ad = (144 + gi) * 132 + mm;
        sD[ad] = 1.f / (1.f + expf(-(sD[ad] + sG[gi])));
    }
    __syncthreads();

    float* zb = g_z + (size_t)b * NCH_ * NSP_ + (size_t)z0 * 1024 + y0 * 32;
    for (int i = tid; i < 144 * 128; i += NT_) {
        int cc = i >> 7, mm = i & 127;
        float v = sD[cc * 132 + mm];
        float o;
        if (cc < 16) o = fmaxf(v + sS[cc], 0.f);
        else {
            int gi = (cc < 64) ? (cc - 16) / 3 : 16 + (cc - 64) / 5;
            o = v * sD[(144 + gi) * 132 + mm];
        }
        zb[(size_t)cc * NSP_ + mm] = o;
    }
}

// ---------------------------------------------------------------------------
// Depthwise 5^3 gaussian, stride2, pad2 -> (16,16,16). grid (8, 144, 4).
// ---------------------------------------------------------------------------
__global__ __launch_bounds__(256)
void lowpass_kernel(float* __restrict__ out)
{
    const int zt = blockIdx.x;
    const int c  = blockIdx.y;
    const int b  = blockIdx.z;
    const int tid = threadIdx.x;

    __shared__ float sZ[7 * 35 * 35];
    __shared__ float sWg[125];

    if (tid < 125) {
        int kw = tid % 5, t = tid / 5;
        int kh = t % 5,  kd = t / 5;
        double g[5], s = 0.0;
#pragma unroll
        for (int r = 0; r < 5; ++r) {
            double d = (double)(r - 2);
            g[r] = exp(-d * d / 1.5);
            s += g[r];
        }
        sWg[tid] = (float)(g[kd] * g[kh] * g[kw] / (s * s * s));
    }

    const int zo0 = 2 * zt;
    const int zi0 = 2 * zo0 - 2;
    const float* zc = g_z + (size_t)(b * NCH_ + c) * NSP_;

    for (int i = tid; i < 7 * 35 * 35; i += 256) {
        int xi = i % 35;
        int t  = i / 35;
        int yi = t % 35;
        int zi = t / 35;
        int gx = xi - 2, gy = yi - 2, gz = zi0 + zi;
        float v = 0.f;
        if ((unsigned)gx < 32u && (unsigned)gy < 32u && (unsigned)gz < 32u)
            v = zc[(gz * 32 + gy) * 32 + gx];
        sZ[i] = v;
    }
    __syncthreads();

    const int xo = tid & 15;
    const int yo = tid >> 4;
#pragma unroll
    for (int dz = 0; dz < 2; ++dz) {
        float sum = 0.f;
#pragma unroll
        for (int kd = 0; kd < 5; ++kd)
#pragma unroll
            for (int kh = 0; kh < 5; ++kh)
#pragma unroll
                for (int kw = 0; kw < 5; ++kw)
                    sum += sWg[(kd * 5 + kh) * 5 + kw] *
                           sZ[((2 * dz + kd) * 35 + (2 * yo + kh)) * 35 +
                              2 * xo + kw];
        out[((size_t)(b * NCH_ + c) * 16 + (zo0 + dz)) * 256 + yo * 16 + xo] = sum;
    }
}

// ---------------------------------------------------------------------------
extern "C" void kernel_launch(void* const* d_in, const int* in_sizes, int n_in,
                              void* d_out, int out_size)
{
    const float* x  = (const float*)d_in[0];   // (4,72,32,32,32)
    const float* W  = (const float*)d_in[1];   // (176,72,5,5,5)
    const float* sb = (const float*)d_in[2];   // (16,)
    const float* gb = (const float*)d_in[3];   // (32,)
    float* out = (float*)d_out;                // (4,144,16,16,16)

    cudaFuncSetAttribute(conv_mma_kernel,
                         cudaFuncAttributeMaxDynamicSharedMemorySize, SMEM_TOTAL);

    prep_kernel<<<6336, 256>>>(W);
    prep_x_kernel<<<36864, 256>>>(x);
    conv_mma_kernel<<<dim3(8, 32, B_), NT_, SMEM_TOTAL>>>(sb, gb);
    lowpass_kernel<<<dim3(8, NCH_, B_), 256>>>(out);
}